// round 15
// baseline (speedup 1.0000x reference)
#include <cuda_runtime.h>

// NSbuilder: emit [L=256, H=512, W=512] float bitstream.
// out[t,h,w] = (thresh > r) where
//   ns_mask = t < new_ns_len[h,w]
//   r       = ns_mask ? rng[t] : rng[t - new_ns_len]
//   thresh  = ns_mask ? src_ns[h,w] : src_st[h,w]
//
// A/B test vs the session champion (43.3/43.5/43.8us wall): byte-identical
// body, ONE token changed — plain default write-back stores instead of
// __stcs evict-first. Hypothesis: normal-priority L2 allocation lets dirty
// lines linger long enough for the DRAM write scheduler to batch row hits,
// vs .cs flushing them evict-first as shallower bursts.

#define HW   (512 * 512)
#define HW4  (HW / 4)
#define LBITS 256
#define TC    64          // t-values per block (gridDim.y = LBITS/TC)

__global__ __launch_bounds__(256) void nsb_kernel(
    const float* __restrict__ src_ns,
    const float* __restrict__ src_st,
    const float* __restrict__ nlen,
    const float* __restrict__ rng,
    float4* __restrict__ out)
{
    // s[i] = rng[i - 256] for i in [256, 512); i in [0,256) is a dummy zone
    // read only when the value is discarded (ns branch taken), so stable-index
    // t - nli + 256 is always in-bounds without a clamp.
    __shared__ float s[512];
    int tid = threadIdx.x;
    s[tid]       = 0.0f;
    s[tid + 256] = rng[tid];
    __syncthreads();

    int p4 = blockIdx.x * 256 + tid;   // float4 pixel-group index [0, 65536)

    float4 ns = reinterpret_cast<const float4*>(src_ns)[p4];
    float4 st = reinterpret_cast<const float4*>(src_st)[p4];
    float4 nl = reinterpret_cast<const float4*>(nlen)[p4];

    // new_ns_len is integral-valued float; (int) matches the reference's
    // astype(int32) on the (t - nl) clip path.
    int n0 = (int)nl.x, n1 = (int)nl.y, n2 = (int)nl.z, n3 = (int)nl.w;

    int tbase = blockIdx.y * TC;

    #pragma unroll 4
    for (int t = tbase; t < tbase + TC; ++t) {
        float rt = s[t + 256];         // rng[t], warp-uniform broadcast
        float tf = (float)t;
        float4 o;

        {
            bool  m  = tf < nl.x;                    // reference: t < new_ns_len (float)
            float r  = m ? rt   : s[t - n0 + 256];
            float th = m ? ns.x : st.x;
            o.x = (th > r) ? 1.0f : 0.0f;
        }
        {
            bool  m  = tf < nl.y;
            float r  = m ? rt   : s[t - n1 + 256];
            float th = m ? ns.y : st.y;
            o.y = (th > r) ? 1.0f : 0.0f;
        }
        {
            bool  m  = tf < nl.z;
            float r  = m ? rt   : s[t - n2 + 256];
            float th = m ? ns.z : st.z;
            o.z = (th > r) ? 1.0f : 0.0f;
        }
        {
            bool  m  = tf < nl.w;
            float r  = m ? rt   : s[t - n3 + 256];
            float th = m ? ns.w : st.w;
            o.w = (th > r) ? 1.0f : 0.0f;
        }

        // Default write-back store (the single changed token vs champion).
        out[(size_t)t * HW4 + (size_t)p4] = o;
    }
}

extern "C" void kernel_launch(void* const* d_in, const int* in_sizes, int n_in,
                              void* d_out, int out_size)
{
    const float* src_ns = (const float*)d_in[0];
    const float* src_st = (const float*)d_in[1];
    const float* nlen   = (const float*)d_in[2];
    const float* rng    = (const float*)d_in[3];
    float4* out = (float4*)d_out;

    dim3 grid(HW4 / 256, LBITS / TC);   // (256, 4)
    nsb_kernel<<<grid, 256>>>(src_ns, src_st, nlen, rng, out);
}

// round 17
// speedup vs baseline: 1.0698x; 1.0698x over previous
#include <cuda_runtime.h>

// NSbuilder: emit [L=256, H=512, W=512] float bitstream.
// out[t,h,w] = (thresh > r) where
//   ns_mask = t < new_ns_len[h,w]
//   r       = ns_mask ? rng[t] : rng[t - new_ns_len]
//   thresh  = ns_mask ? src_ns[h,w] : src_st[h,w]
//
// FINAL — session champion, reproduced 3x (43.3/43.5/43.8us wall).
// Pure 268MB write stream at ~6.2TB/s sustained = effective HBM3e write
// ceiling. Falsified one-variable alternatives (all >= +2.1us): register
// __brev rng, TMA bulk stores (x2), write-through, single-wave reg squeeze,
// L2 evict_last pinning, 2-pixel/thread MLP, default write-back stores.
// __stcs evict-first is load-bearing (+2.7us without it).

#define HW   (512 * 512)
#define HW4  (HW / 4)
#define LBITS 256
#define TC    64          // t-values per block (gridDim.y = LBITS/TC)

__global__ __launch_bounds__(256) void nsb_kernel(
    const float* __restrict__ src_ns,
    const float* __restrict__ src_st,
    const float* __restrict__ nlen,
    const float* __restrict__ rng,
    float4* __restrict__ out)
{
    // s[i] = rng[i - 256] for i in [256, 512); i in [0,256) is a dummy zone
    // read only when the value is discarded (ns branch taken), so stable-index
    // t - nli + 256 is always in-bounds without a clamp.
    __shared__ float s[512];
    int tid = threadIdx.x;
    s[tid]       = 0.0f;
    s[tid + 256] = rng[tid];
    __syncthreads();

    int p4 = blockIdx.x * 256 + tid;   // float4 pixel-group index [0, 65536)

    float4 ns = reinterpret_cast<const float4*>(src_ns)[p4];
    float4 st = reinterpret_cast<const float4*>(src_st)[p4];
    float4 nl = reinterpret_cast<const float4*>(nlen)[p4];

    // new_ns_len is integral-valued float; (int) matches the reference's
    // astype(int32) on the (t - nl) clip path.
    int n0 = (int)nl.x, n1 = (int)nl.y, n2 = (int)nl.z, n3 = (int)nl.w;

    int tbase = blockIdx.y * TC;

    #pragma unroll 4
    for (int t = tbase; t < tbase + TC; ++t) {
        float rt = s[t + 256];         // rng[t], warp-uniform broadcast
        float tf = (float)t;
        float4 o;

        {
            bool  m  = tf < nl.x;                    // reference: t < new_ns_len (float)
            float r  = m ? rt   : s[t - n0 + 256];
            float th = m ? ns.x : st.x;
            o.x = (th > r) ? 1.0f : 0.0f;
        }
        {
            bool  m  = tf < nl.y;
            float r  = m ? rt   : s[t - n1 + 256];
            float th = m ? ns.y : st.y;
            o.y = (th > r) ? 1.0f : 0.0f;
        }
        {
            bool  m  = tf < nl.z;
            float r  = m ? rt   : s[t - n2 + 256];
            float th = m ? ns.z : st.z;
            o.z = (th > r) ? 1.0f : 0.0f;
        }
        {
            bool  m  = tf < nl.w;
            float r  = m ? rt   : s[t - n3 + 256];
            float th = m ? ns.w : st.w;
            o.w = (th > r) ? 1.0f : 0.0f;
        }

        // Streaming store: 256 MB with zero reuse — evict-first, keep L2 clean.
        __stcs(&out[(size_t)t * HW4 + (size_t)p4], o);
    }
}

extern "C" void kernel_launch(void* const* d_in, const int* in_sizes, int n_in,
                              void* d_out, int out_size)
{
    const float* src_ns = (const float*)d_in[0];
    const float* src_st = (const float*)d_in[1];
    const float* nlen   = (const float*)d_in[2];
    const float* rng    = (const float*)d_in[3];
    float4* out = (float4*)d_out;

    dim3 grid(HW4 / 256, LBITS / TC);   // (256, 4)
    nsb_kernel<<<grid, 256>>>(src_ns, src_st, nlen, rng, out);
}